// round 16
// baseline (speedup 1.0000x reference)
#include <cuda_runtime.h>
#include <cuda_fp16.h>

#define NB 8192
#define NK 16
#define ND 512
#define NS 4

// ---------------- scratch (device globals: allocation-free) ----------------
__device__ float buf_mkf [(size_t)NB * NK];
__device__ float buf_ws  [(size_t)NB * 2048];        // fp32 (attn1 residual)
// fp16 operands
__device__ __half hid_h  [(size_t)NB * NK * ND];
__device__ __half ctx_h  [(size_t)NB * ND];
__device__ __half h1_h   [(size_t)NB * 1024];
__device__ __half ws_h   [(size_t)NB * 2048];
__device__ __half wsu_h  [(size_t)NB * NS * ND];
__device__ __half qw_h   [(size_t)NB * NS * ND];     // ws @ (wq@wk^T)
__device__ __half pool_h [(size_t)NB * NS * ND];     // attn_w @ hidden
__device__ __half poov_h [(size_t)NB * NS * ND];     // pooled @ wv
__device__ __half krv_h  [(size_t)NB * NS * 1024];   // [Kt|Vro]
__device__ __half wh_gw1 [512 * 1024];
__device__ __half wh_gw2 [1024 * 2048];
__device__ __half wh_wv  [512 * 512];
__device__ __half wh_wq  [512 * 512];
__device__ __half wh_rk  [512 * 512];
__device__ __half wh_rv  [512 * 512];
__device__ __half wh_ro  [512 * 512];
__device__ __half wh_wkT [512 * 512];                // wk^T
__device__ __half wh_rqT [512 * 512];                // rq^T
__device__ __half wqwk_h [512 * 512];                // wq @ wk^T
__device__ __half wh_p2  [512 * 1024];               // [rk@rq^T | rv@ro]

__device__ __forceinline__ float warp_sum(float v) {
    #pragma unroll
    for (int o = 16; o > 0; o >>= 1) v += __shfl_xor_sync(0xffffffffu, v, o);
    return v;
}
__device__ __forceinline__ float4 h4f(uint2 v) {
    __half2 a = *(__half2*)&v.x, b = *(__half2*)&v.y;
    float2 fa = __half22float2(a), fb = __half22float2(b);
    return make_float4(fa.x, fa.y, fb.x, fb.y);
}

// ---------------- PTX helpers ------------------------------------------------
__device__ __forceinline__ void mma_f16(float c[4], const unsigned a[4], const unsigned b[2]) {
    asm volatile(
        "mma.sync.aligned.m16n8k16.row.col.f32.f16.f16.f32 "
        "{%0,%1,%2,%3}, {%4,%5,%6,%7}, {%8,%9}, {%0,%1,%2,%3};"
        : "+f"(c[0]), "+f"(c[1]), "+f"(c[2]), "+f"(c[3])
        : "r"(a[0]), "r"(a[1]), "r"(a[2]), "r"(a[3]), "r"(b[0]), "r"(b[1]));
}
__device__ __forceinline__ void ldsm_x4(unsigned r[4], unsigned saddr) {
    asm volatile("ldmatrix.sync.aligned.m8n8.x4.shared.b16 {%0,%1,%2,%3}, [%4];"
        : "=r"(r[0]), "=r"(r[1]), "=r"(r[2]), "=r"(r[3]) : "r"(saddr));
}
__device__ __forceinline__ void ldsm_x4t(unsigned r[4], unsigned saddr) {
    asm volatile("ldmatrix.sync.aligned.m8n8.x4.trans.shared.b16 {%0,%1,%2,%3}, [%4];"
        : "=r"(r[0]), "=r"(r[1]), "=r"(r[2]), "=r"(r[3]) : "r"(saddr));
}
__device__ __forceinline__ void cp_async16(unsigned saddr, const void* gaddr) {
    asm volatile("cp.async.cg.shared.global [%0], [%1], 16;" :: "r"(saddr), "l"(gaddr));
}
__device__ __forceinline__ void cp_commit() { asm volatile("cp.async.commit_group;"); }
template <int N>
__device__ __forceinline__ void cp_wait() {
    asm volatile("cp.async.wait_group %0;" :: "n"(N));
}

// ---------------- fp32 -> fp16 bulk convert ----------------------------------
__global__ void f2h_kernel(const float4* __restrict__ src, uint4* __restrict__ dst) {
    const size_t i = (size_t)blockIdx.x * 256 + threadIdx.x;
    float4 a = src[2 * i], b = src[2 * i + 1];
    __half2 h0 = __float22half2_rn(make_float2(a.x, a.y));
    __half2 h1 = __float22half2_rn(make_float2(a.z, a.w));
    __half2 h2 = __float22half2_rn(make_float2(b.x, b.y));
    __half2 h3 = __float22half2_rn(make_float2(b.z, b.w));
    uint4 o;
    o.x = *(unsigned*)&h0; o.y = *(unsigned*)&h1;
    o.z = *(unsigned*)&h2; o.w = *(unsigned*)&h3;
    dst[i] = o;
}
// five 512x512 weights in one launch (grid.y selects)
__global__ void f2h5_kernel(const float* w0, const float* w1, const float* w2,
                            const float* w3, const float* w4) {
    const float* srcs[5] = {w0, w1, w2, w3, w4};
    __half* dsts[5] = {wh_wq, wh_rk, wh_rv, wh_ro, wh_wv};
    const float4* s = (const float4*)srcs[blockIdx.y];
    uint4* d = (uint4*)dsts[blockIdx.y];
    const size_t i = (size_t)blockIdx.x * 256 + threadIdx.x;
    float4 a = s[2 * i], b = s[2 * i + 1];
    __half2 h0 = __float22half2_rn(make_float2(a.x, a.y));
    __half2 h1 = __float22half2_rn(make_float2(a.z, a.w));
    __half2 h2 = __float22half2_rn(make_float2(b.x, b.y));
    __half2 h3 = __float22half2_rn(make_float2(b.z, b.w));
    uint4 o;
    o.x = *(unsigned*)&h0; o.y = *(unsigned*)&h1;
    o.z = *(unsigned*)&h2; o.w = *(unsigned*)&h3;
    d[i] = o;
}
// 512x512 fp32 -> fp16 transpose (wk -> wkT, rq -> rqT); grid.z selects
__global__ void tr_f2h_kernel(const float* __restrict__ wk, const float* __restrict__ rq) {
    __shared__ float t[32][33];
    const float* src = blockIdx.z ? rq : wk;
    __half* dst = blockIdx.z ? wh_rqT : wh_wkT;
    const int bx = blockIdx.x * 32, by = blockIdx.y * 32;
    const int tx = threadIdx.x, ty = threadIdx.y;
    #pragma unroll
    for (int i = 0; i < 32; i += 8)
        t[ty + i][tx] = src[(size_t)(by + ty + i) * 512 + bx + tx];
    __syncthreads();
    #pragma unroll
    for (int i = 0; i < 32; i += 8)
        dst[(size_t)(bx + ty + i) * 512 + by + tx] = __float2half(t[tx][ty + i]);
}

// ---------------- masked context pooling + hidden->fp16 ----------------------
__global__ void ctx_kernel(const float* __restrict__ hidden, const void* mask_raw) {
    const int b = blockIdx.x;
    const int tid = threadIdx.x;              // 128 threads
    __shared__ float sm[NK];
    __shared__ int smode;
    if (tid == 0) {
        const unsigned char* p = (const unsigned char*)mask_raw;
        int mode = 0;
        for (int i = 0; i < 512; ++i) {
            unsigned char v = p[i];
            if (!v) continue;
            if (v != 1u) { mode = 2; break; }
            if (i & 3)   { mode = 1; break; }
        }
        smode = mode;
    }
    __syncthreads();
    const int mode = smode;
    if (tid < NK) {
        int idx = b * NK + tid;
        float m;
        if (mode == 1)      m = ((const unsigned char*)mask_raw)[idx] ? 1.f : 0.f;
        else if (mode == 0) m = ((const int*)mask_raw)[idx] ? 1.f : 0.f;
        else                m = ((const float*)mask_raw)[idx];
        sm[tid] = m;
        buf_mkf[idx] = m;
    }
    __syncthreads();
    float n = 0.f;
    #pragma unroll
    for (int k = 0; k < NK; ++k) n += sm[k];
    const float inv = 1.f / fmaxf(n, 1.f);
    float4 acc = make_float4(0.f, 0.f, 0.f, 0.f);
    const float4* h4 = (const float4*)(hidden + (size_t)b * NK * ND);
    #pragma unroll
    for (int k = 0; k < NK; ++k) {
        float m = sm[k];
        float4 v = h4[k * 128 + tid];
        acc.x += m * v.x; acc.y += m * v.y; acc.z += m * v.z; acc.w += m * v.w;
        __half2 a0 = __float22half2_rn(make_float2(v.x, v.y));
        __half2 a1 = __float22half2_rn(make_float2(v.z, v.w));
        uint2 ho; ho.x = *(unsigned*)&a0; ho.y = *(unsigned*)&a1;
        *(uint2*)&hid_h[((size_t)b * NK + k) * ND + tid * 4] = ho;
    }
    __half2 h0 = __float22half2_rn(make_float2(acc.x * inv, acc.y * inv));
    __half2 h1 = __float22half2_rn(make_float2(acc.z * inv, acc.w * inv));
    uint2 o; o.x = *(unsigned*)&h0; o.y = *(unsigned*)&h1;
    *(uint2*)&ctx_h[(size_t)b * ND + tid * 4] = o;
}

// ---------------- FP16 tensor-core GEMM, 128x128 tile, BK=32 -----------------
// (R14-proven config: 8 warps, 64x32 warp tile, 4-stage cp.async, 2 CTA/SM)
#define ASTRH 40
#define BSTRH 136
#define NSTG 4
#define ABYTES (128 * ASTRH * 2)
#define BBYTES (32 * BSTRH * 2)
#define STGB   (ABYTES + BBYTES)
#define HSMEM  (NSTG * STGB)

__global__ void __launch_bounds__(256, 2)
hgemm(const __half* __restrict__ A, const __half* __restrict__ B,
      float* __restrict__ C, __half* __restrict__ Ch, int M, int N, int K, int ldc,
      const float* __restrict__ bias1, const float* __restrict__ bias2,
      int do_gelu) {
    extern __shared__ __align__(16) char smem[];

    const int bm = blockIdx.y * 128;
    const int bn = blockIdx.x * 128;
    const int tid  = threadIdx.x;
    const int warp = tid >> 5;
    const int lane = tid & 31;
    const int gid  = lane >> 2;
    const int tig  = lane & 3;
    const int wm   = (warp >> 2) * 64;
    const int wn   = (warp & 3) * 32;

    const unsigned sBase = (unsigned)__cvta_generic_to_shared(smem);
    const unsigned aOff =
        (unsigned)(((wm + ((lane >> 3) & 1) * 8 + (lane & 7)) * ASTRH + (lane >> 4) * 8) * 2);
    const unsigned bOff =
        (unsigned)(((lane & 15) * BSTRH + wn + ((lane >> 4) * 8)) * 2);

    float acc[4][4][4];
    #pragma unroll
    for (int i = 0; i < 4; ++i)
        #pragma unroll
        for (int j = 0; j < 4; ++j)
            #pragma unroll
            for (int r = 0; r < 4; ++r) acc[i][j][r] = 0.f;

    const int nk = K >> 5;

    auto fill = [&](int st, int k0) {
        const unsigned stb = sBase + (unsigned)(st * STGB);
        #pragma unroll
        for (int it = 0; it < 2; ++it) {
            const int idx = tid + 256 * it;
            const int row = idx >> 2, kq = (idx & 3) * 8;
            cp_async16(stb + (unsigned)((row * ASTRH + kq) * 2),
                       A + (size_t)(bm + row) * K + k0 + kq);
        }
        #pragma unroll
        for (int it = 0; it < 2; ++it) {
            const int idx = tid + 256 * it;
            const int kr = idx >> 4, n8 = (idx & 15) * 8;
            cp_async16(stb + (unsigned)(ABYTES + (kr * BSTRH + n8) * 2),
                       B + (size_t)(k0 + kr) * N + bn + n8);
        }
    };

    #pragma unroll
    for (int s = 0; s < NSTG - 1; ++s) {
        fill(s, s * 32);
        cp_commit();
    }
    cp_wait<NSTG - 2>();
    __syncthreads();

    for (int kt = 0; kt < nk; ++kt) {
        const int st = kt & (NSTG - 1);
        const unsigned stA = sBase + (unsigned)(st * STGB);
        const unsigned stB = stA + ABYTES;

        #pragma unroll
        for (int ks = 0; ks < 2; ++ks) {
            unsigned afr[4][4], bfr[4][2];
            #pragma unroll
            for (int i = 0; i < 4; ++i)
                ldsm_x4(afr[i], stA + aOff + (unsigned)(i * 16 * ASTRH * 2 + ks * 32));
            #pragma unroll
            for (int jj = 0; jj < 2; ++jj) {
                unsigned r[4];
                ldsm_x4t(r, stB + bOff + (unsigned)(ks * 16 * BSTRH * 2 + jj * 32));
                bfr[2 * jj][0] = r[0]; bfr[2 * jj][1] = r[1];
                bfr[2 * jj + 1][0] = r[2]; bfr[2 * jj + 1][1] = r[3];
            }
            #pragma unroll
            for (int i = 0; i < 4; ++i)
                #pragma unroll
                for (int j = 0; j < 4; ++j)
                    mma_f16(acc[i][j], afr[i], bfr[j]);
        }

        if (kt + NSTG - 1 < nk)
            fill((kt + NSTG - 1) & (NSTG - 1), (kt + NSTG - 1) << 5);
        cp_commit();
        cp_wait<NSTG - 2>();
        __syncthreads();
    }

    #pragma unroll
    for (int i = 0; i < 4; ++i) {
        #pragma unroll
        for (int j = 0; j < 4; ++j) {
            #pragma unroll
            for (int half = 0; half < 2; ++half) {
                const int row = bm + wm + i * 16 + gid + half * 8;
                const int col = bn + wn + j * 8 + tig * 2;
                float v0 = acc[i][j][half * 2 + 0];
                float v1 = acc[i][j][half * 2 + 1];
                if (bias1) { v0 += bias1[col]; v1 += bias1[col + 1]; }
                if (bias2) { v0 += bias2[col]; v1 += bias2[col + 1]; }
                if (do_gelu) {
                    v0 = 0.5f * v0 * (1.f + erff(v0 * 0.70710678118654752f));
                    v1 = 0.5f * v1 * (1.f + erff(v1 * 0.70710678118654752f));
                }
                if (C)
                    *(float2*)(C + (size_t)row * ldc + col) = make_float2(v0, v1);
                if (Ch) {
                    __half2 hv = __float22half2_rn(make_float2(v0, v1));
                    *(__half2*)(Ch + (size_t)row * ldc + col) = hv;
                }
            }
        }
    }
}

// ---------------- attn1a: logits, masked softmax, pooled = attn_w @ hidden ---
__global__ void __launch_bounds__(256) attn1a_kernel() {
    __shared__ __align__(16) float sq[NS * ND];
    __shared__ __align__(16) float sh[NK * ND];
    __shared__ float slog[64], swt[64];
    const int b = blockIdx.x;
    const int tid = threadIdx.x;
    const int warp = tid >> 5;
    const int lane = tid & 31;

    {
        #pragma unroll
        for (int i = 0; i < 2; ++i) {
            const int idx = tid + 256 * i;
            const int s = idx >> 7, c4 = idx & 127;
            uint2 q = *(const uint2*)&qw_h[((size_t)b * NS + s) * ND + 4 * c4];
            ((float4*)sq)[idx] = h4f(q);
        }
        #pragma unroll
        for (int i = 0; i < 8; ++i) {
            const int idx = tid + 256 * i;
            const int k = idx >> 7, c4 = idx & 127;
            uint2 v = *(const uint2*)&hid_h[((size_t)(b * NK + k)) * ND + 4 * c4];
            ((float4*)sh)[idx] = h4f(v);
        }
    }
    __syncthreads();

    {
        const int p0 = warp * 8;
        float acc[8];
        #pragma unroll
        for (int u = 0; u < 8; ++u) acc[u] = 0.f;
        #pragma unroll
        for (int j = 0; j < 4; ++j) {
            const int c = lane + 32 * j;
            #pragma unroll
            for (int u = 0; u < 8; ++u) {
                const int p = p0 + u, s = p >> 4, k = p & 15;
                float4 q4 = ((const float4*)sq)[s * 128 + c];
                float4 k4 = ((const float4*)sh)[k * 128 + c];
                acc[u] += q4.x * k4.x + q4.y * k4.y + q4.z * k4.z + q4.w * k4.w;
            }
        }
        #pragma unroll
        for (int u = 0; u < 8; ++u) acc[u] = warp_sum(acc[u]);
        if (lane == 0) {
            #pragma unroll
            for (int u = 0; u < 8; ++u) slog[p0 + u] = acc[u];
        }
    }
    __syncthreads();

    if (tid < NS) {
        const int s = tid;
        const float scale = 0.04419417382415922f;
        float lg[NK];
        float mx = -1e30f;
        int any = 0;
        #pragma unroll
        for (int k = 0; k < NK; ++k) {
            float m = buf_mkf[b * NK + k];
            float l = (m > 0.5f) ? slog[s * NK + k] * scale : -1e30f;
            if (m > 0.5f) any = 1;
            lg[k] = l;
            mx = fmaxf(mx, l);
        }
        float den = 0.f;
        #pragma unroll
        for (int k = 0; k < NK; ++k) { lg[k] = expf(lg[k] - mx); den += lg[k]; }
        const float inv = any ? (1.f / den) : 0.f;
        #pragma unroll
        for (int k = 0; k < NK; ++k) swt[s * NK + k] = lg[k] * inv;
    }
    __syncthreads();

    {
        #pragma unroll
        for (int i = 0; i < 2; ++i) {
            const int idx = tid + 256 * i;
            const int s = idx >> 7, c4 = idx & 127;
            float4 o = make_float4(0.f, 0.f, 0.f, 0.f);
            #pragma unroll
            for (int k = 0; k < NK; ++k) {
                const float w = swt[s * NK + k];
                float4 v4 = ((const float4*)sh)[k * 128 + c4];
                o.x += w * v4.x; o.y += w * v4.y; o.z += w * v4.z; o.w += w * v4.w;
            }
            __half2 h0 = __float22half2_rn(make_float2(o.x, o.y));
            __half2 h1 = __float22half2_rn(make_float2(o.z, o.w));
            uint2 oh; oh.x = *(unsigned*)&h0; oh.y = *(unsigned*)&h1;
            *(uint2*)&pool_h[((size_t)b * NS + s) * ND + 4 * c4] = oh;
        }
    }
}

// ---------------- attn1b: wsu = LN(ws + pooledv) ------------------------------
__global__ void __launch_bounds__(128) attn1b_kernel(const float* __restrict__ gamma,
                                                     const float* __restrict__ beta) {
    const int b = blockIdx.x;
    const int warp = threadIdx.x >> 5;
    const int lane = threadIdx.x & 31;
    const int s = warp;

    const float4* wsb = (const float4*)(buf_ws + (size_t)b * 2048 + s * ND);
    const __half* pv = poov_h + ((size_t)b * NS + s) * ND;
    float4 y[4];
    #pragma unroll
    for (int j = 0; j < 4; ++j) {
        const int c4 = lane + 32 * j;
        float4 a = wsb[c4];
        float4 p = h4f(*(const uint2*)(pv + 4 * c4));
        y[j] = make_float4(a.x + p.x, a.y + p.y, a.z + p.z, a.w + p.w);
    }
    float sum = 0.f;
    #pragma unroll
    for (int j = 0; j < 4; ++j) sum += y[j].x + y[j].y + y[j].z + y[j].w;
    const float mu = warp_sum(sum) * (1.f / ND);
    float sqs = 0.f;
    #pragma unroll
    for (int j = 0; j < 4; ++j) {
        float cx = y[j].x - mu, cy = y[j].y - mu, cz = y[j].z - mu, cw = y[j].w - mu;
        sqs += cx * cx + cy * cy + cz * cz + cw * cw;
    }
    const float var = warp_sum(sqs) * (1.f / ND);
    const float rstd = rsqrtf(var + 1e-5f);
    #pragma unroll
    for (int j = 0; j < 4; ++j) {
        const int d4 = lane + 32 * j;
        float4 g4 = ((const float4*)gamma)[d4];
        float4 b4 = ((const float4*)beta)[d4];
        float4 o;
        o.x = (y[j].x - mu) * rstd * g4.x + b4.x;
        o.y = (y[j].y - mu) * rstd * g4.y + b4.y;
        o.z = (y[j].z - mu) * rstd * g4.z + b4.z;
        o.w = (y[j].w - mu) * rstd * g4.w + b4.w;
        __half2 h0 = __float22half2_rn(make_float2(o.x, o.y));
        __half2 h1 = __float22half2_rn(make_float2(o.z, o.w));
        uint2 oh; oh.x = *(unsigned*)&h0; oh.y = *(unsigned*)&h1;
        *(uint2*)&wsu_h[((size_t)b * NS + s) * ND + d4 * 4] = oh;
    }
}

// ---------------- attention #2: single fp32 hidden read, +residual, LN -------
__global__ void __launch_bounds__(512) attn2_kernel(const float* __restrict__ hidden,
                                                    const float* __restrict__ gamma,
                                                    const float* __restrict__ beta,
                                                    float* __restrict__ out) {
    __shared__ __align__(16) float skr[NS * ND];
    __shared__ __align__(16) float svr[NS * ND];
    const int b = blockIdx.x;
    const int tid = threadIdx.x;
    const int warp = tid >> 5;          // token k
    const int lane = tid & 31;

    {
        const int s = tid >> 7, c4 = tid & 127;
        const __half* base = krv_h + (size_t)(b * NS + s) * 1024;
        ((float4*)skr)[tid] = h4f(*(const uint2*)(base + 4 * c4));
        ((float4*)svr)[tid] = h4f(*(const uint2*)(base + 512 + 4 * c4));
    }
    __syncthreads();

    const int k = warp;
    // one fp32 load of hidden row; reused for logits AND residual
    const float4* h4p = (const float4*)(hidden + (size_t)(b * NK + k) * ND);
    float4 hreg[4];
    #pragma unroll
    for (int j = 0; j < 4; ++j) hreg[j] = h4p[lane + 32 * j];

    float acc[4] = {0.f, 0.f, 0.f, 0.f};
    #pragma unroll
    for (int j = 0; j < 4; ++j) {
        const int c = lane + 32 * j;
        const float4 q = hreg[j];
        #pragma unroll
        for (int s = 0; s < 4; ++s) {
            float4 kk = ((const float4*)skr)[s * 128 + c];
            acc[s] += q.x * kk.x + q.y * kk.y + q.z * kk.z + q.w * kk.w;
        }
    }
    #pragma unroll
    for (int s = 0; s < 4; ++s) acc[s] = warp_sum(acc[s]);

    const float scale = 0.04419417382415922f;
    float w[4];
    float mx = -1e30f;
    #pragma unroll
    for (int s = 0; s < 4; ++s) { w[s] = acc[s] * scale; mx = fmaxf(mx, w[s]); }
    float den = 0.f;
    #pragma unroll
    for (int s = 0; s < 4; ++s) { w[s] = expf(w[s] - mx); den += w[s]; }
    const float inv = 1.f / den;
    #pragma unroll
    for (int s = 0; s < 4; ++s) w[s] *= inv;

    float4 y[4];
    #pragma unroll
    for (int j = 0; j < 4; ++j) {
        const int c4 = lane + 32 * j;
        float4 v0 = ((const float4*)svr)[c4];
        float4 v1 = ((const float4*)svr)[128 + c4];
        float4 v2 = ((const float4*)svr)[256 + c4];
        float4 v3 = ((const float4*)svr)[384 + c4];
        const float4 h = hreg[j];
        y[j].x = h.x + w[0] * v0.x + w[1] * v1.x + w[2] * v2.x + w[3] * v3.x;
        y[j].y = h.y + w[0] * v0.y + w[1] * v1.y + w[2] * v2.y + w[3] * v3.y;
        y[j].z = h.z + w[0] * v0.z + w[1] * v1.z + w[2] * v2.z + w[3] * v3.z;
        y[j].w = h.w + w[0] * v0.w + w[1] * v1.w + w[2] * v2.w + w[3] * v3.w;
    }
    float sum = 0.f;
    #pragma unroll
    for (int j = 0; j < 4; ++j) sum += y[j].x + y[j].y + y[j].z + y[j].w;
    const float mu = warp_sum(sum) * (1.f / ND);
    float sqs = 0.f;
    #pragma unroll
    for (int j = 0; j < 4; ++j) {
        float cx = y[j].x - mu, cy = y[j].y - mu, cz = y[j].z - mu, cw = y[j].w - mu;
        sqs += cx * cx + cy * cy + cz * cz + cw * cw;
    }
    const float var = warp_sum(sqs) * (1.f / ND);
    const float rstd = rsqrtf(var + 1e-5f);
    float4* outp = (float4*)(out + (size_t)(b * NK + k) * ND);
    #pragma unroll
    for (int j = 0; j < 4; ++j) {
        const int d4 = lane + 32 * j;
        float4 g4 = ((const float4*)gamma)[d4];
        float4 bb = ((const float4*)beta)[d4];
        float4 o;
        o.x = (y[j].x - mu) * rstd * g4.x + bb.x;
        o.y = (y[j].y - mu) * rstd * g4.y + bb.y;
        o.z = (y[j].z - mu) * rstd * g4.z + bb.z;
        o.w = (y[j].w - mu) * rstd * g4.w + bb.w;
        outp[d4] = o;
    }
}

// ---------------- host launcher ----------------------------------------------
extern "C" void kernel_launch(void* const* d_in, const int* in_sizes, int n_in,
                              void* d_out, int out_size) {
    const float* hidden   = (const float*)d_in[0];
    const void*  mask     = d_in[1];
    const float* fallback = (const float*)d_in[2];
    const float* gw1      = (const float*)d_in[3];
    const float* gb1      = (const float*)d_in[4];
    const float* gw2      = (const float*)d_in[5];
    const float* gb2      = (const float*)d_in[6];
    const float* wq       = (const float*)d_in[7];
    const float* wk       = (const float*)d_in[8];
    const float* wv       = (const float*)d_in[9];
    const float* rq       = (const float*)d_in[10];
    const float* rk       = (const float*)d_in[11];
    const float* rv       = (const float*)d_in[12];
    const float* ro       = (const float*)d_in[13];
    const float* g_ws_w   = (const float*)d_in[14];
    const float* b_ws_w   = (const float*)d_in[15];
    const float* g_out_w  = (const float*)d_in[16];
    const float* b_out_w  = (const float*)d_in[17];
    float* out = (float*)d_out;

    float *ws;
    __half *hidh, *ctxh, *h1h, *wsh, *wsuh, *qwh, *poolh, *poovh, *krvh;
    __half *wgw1, *wgw2, *wwvh, *wwqh, *wrkh, *wrvh, *wroh;
    __half *wkTh, *rqTh, *wqwkh, *wp2h;
    cudaGetSymbolAddress((void**)&ws,   buf_ws);
    cudaGetSymbolAddress((void**)&hidh, hid_h);
    cudaGetSymbolAddress((void**)&ctxh, ctx_h);
    cudaGetSymbolAddress((void**)&h1h,  h1_h);
    cudaGetSymbolAddress((void**)&wsh,  ws_h);
    cudaGetSymbolAddress((void**)&wsuh, wsu_h);
    cudaGetSymbolAddress((void**)&qwh,  qw_h);
    cudaGetSymbolAddress((void**)&poolh, pool_h);
    cudaGetSymbolAddress((void**)&poovh, poov_h);
    cudaGetSymbolAddress((void**)&krvh, krv_h);
    cudaGetSymbolAddress((void**)&wgw1, wh_gw1);
    cudaGetSymbolAddress((void**)&wgw2, wh_gw2);
    cudaGetSymbolAddress((void**)&wwvh, wh_wv);
    cudaGetSymbolAddress((void**)&wwqh, wh_wq);
    cudaGetSymbolAddress((void**)&wrkh, wh_rk);
    cudaGetSymbolAddress((void**)&wrvh, wh_rv);
    cudaGetSymbolAddress((void**)&wroh, wh_ro);
    cudaGetSymbolAddress((void**)&wkTh, wh_wkT);
    cudaGetSymbolAddress((void**)&rqTh, wh_rqT);
    cudaGetSymbolAddress((void**)&wqwkh, wqwk_h);
    cudaGetSymbolAddress((void**)&wp2h, wh_p2);

    cudaFuncSetAttribute(hgemm, cudaFuncAttributeMaxDynamicSharedMemorySize, HSMEM);

    // weight conversions + composed weights (written straight into wh_p2)
    f2h_kernel<<<256,  256>>>((const float4*)gw1, (uint4*)wgw1);
    f2h_kernel<<<1024, 256>>>((const float4*)gw2, (uint4*)wgw2);
    f2h5_kernel<<<dim3(128, 5), 256>>>(wq, rk, rv, ro, wv);
    tr_f2h_kernel<<<dim3(16, 16, 2), dim3(32, 8)>>>(wk, rq);
    hgemm<<<dim3(4, 4), 256, HSMEM>>>(wwqh, wkTh, nullptr, wqwkh, 512, 512, 512, 512,
                                      nullptr, nullptr, 0);
    hgemm<<<dim3(4, 4), 256, HSMEM>>>(wrkh, rqTh, nullptr, wp2h, 512, 512, 512, 1024,
                                      nullptr, nullptr, 0);
    hgemm<<<dim3(4, 4), 256, HSMEM>>>(wrvh, wroh, nullptr, wp2h + 512, 512, 512, 512, 1024,
                                      nullptr, nullptr, 0);

    // context pooling (also emits hid_h)
    ctx_kernel<<<NB, 128>>>(hidden, mask);

    // h1 = gelu(ctx @ gw1 + gb1)             (8192 x 1024) -> fp16
    hgemm<<<dim3(8, 64), 256, HSMEM>>>(ctxh, wgw1, nullptr, h1h, 8192, 1024, 512, 1024,
                                       gb1, nullptr, 1);
    // ws = h1 @ gw2 + gb2 + fallback         (8192 x 2048) -> fp32 + fp16
    hgemm<<<dim3(16, 64), 256, HSMEM>>>(h1h, wgw2, ws, wsh, 8192, 2048, 1024, 2048,
                                        gb2, fallback, 0);
    // Qw' = ws @ (wq@wk^T)                   (32768 x 512) -> fp16
    hgemm<<<dim3(4, 256), 256, HSMEM>>>(wsh, wqwkh, nullptr, qwh, 32768, 512, 512, 512,
                                        nullptr, nullptr, 0);
    // attn1a: softmax + pooled = attn_w @ hidden
    attn1a_kernel<<<NB, 256>>>();
    // pooledv = pooled @ wv                  (32768 x 512) -> fp16
    hgemm<<<dim3(4, 256), 256, HSMEM>>>(poolh, wwvh, nullptr, poovh, 32768, 512, 512, 512,
                                        nullptr, nullptr, 0);
    // attn1b: wsu = LN(ws + pooledv)
    attn1b_kernel<<<NB, 128>>>(g_ws_w, b_ws_w);
    // [Kt|Vro] = ws_upd @ [rk@rq^T | rv@ro]  (32768 x 1024) -> fp16
    hgemm<<<dim3(8, 256), 256, HSMEM>>>(wsuh, wp2h, nullptr, krvh, 32768, 1024, 512, 1024,
                                        nullptr, nullptr, 0);
    // attention #2 + residual + layernorm -> out
    attn2_kernel<<<NB, 512>>>(hidden, g_out_w, b_out_w, out);
}

// round 17
// speedup vs baseline: 1.5131x; 1.5131x over previous
#include <cuda_runtime.h>
#include <cuda_fp16.h>

#define NB 8192
#define NK 16
#define ND 512
#define NS 4

// ---------------- scratch (device globals: allocation-free) ----------------
__device__ float buf_mkf [(size_t)NB * NK];
__device__ float buf_ws  [(size_t)NB * 2048];        // fp32 (attn1 residual)
// fp16 operands
__device__ __half hid_h  [(size_t)NB * NK * ND];
__device__ __half ctx_h  [(size_t)NB * ND];
__device__ __half h1_h   [(size_t)NB * 1024];
__device__ __half ws_h   [(size_t)NB * 2048];
__device__ __half wsu_h  [(size_t)NB * NS * ND];
__device__ __half qw_h   [(size_t)NB * NS * ND];     // ws @ (wq@wk^T)
__device__ __half pool_h [(size_t)NB * NS * ND];     // attn_w @ hidden
__device__ __half poov_h [(size_t)NB * NS * ND];     // pooled @ wv
__device__ __half krv_h  [(size_t)NB * NS * 1024];   // [Kt|Vro]
__device__ __half wh_gw1 [512 * 1024];
__device__ __half wh_gw2 [1024 * 2048];
__device__ __half wh_wv  [512 * 512];
__device__ __half wh_wq  [512 * 512];
__device__ __half wh_rk  [512 * 512];
__device__ __half wh_rv  [512 * 512];
__device__ __half wh_ro  [512 * 512];
__device__ __half wh_wkT [512 * 512];                // wk^T
__device__ __half wh_rqT [512 * 512];                // rq^T
__device__ __half wqwk_h [512 * 512];                // wq @ wk^T
__device__ __half rkrq_h [512 * 512];                // rk @ rq^T
__device__ __half rvro_h [512 * 512];                // rv @ ro
__device__ __half wh_p2  [512 * 1024];               // [rkrq | rvro]

__device__ __forceinline__ float warp_sum(float v) {
    #pragma unroll
    for (int o = 16; o > 0; o >>= 1) v += __shfl_xor_sync(0xffffffffu, v, o);
    return v;
}
__device__ __forceinline__ float4 h4f(uint2 v) {
    __half2 a = *(__half2*)&v.x, b = *(__half2*)&v.y;
    float2 fa = __half22float2(a), fb = __half22float2(b);
    return make_float4(fa.x, fa.y, fb.x, fb.y);
}

// ---------------- PTX helpers ------------------------------------------------
__device__ __forceinline__ void mma_f16(float c[4], const unsigned a[4], const unsigned b[2]) {
    asm volatile(
        "mma.sync.aligned.m16n8k16.row.col.f32.f16.f16.f32 "
        "{%0,%1,%2,%3}, {%4,%5,%6,%7}, {%8,%9}, {%0,%1,%2,%3};"
        : "+f"(c[0]), "+f"(c[1]), "+f"(c[2]), "+f"(c[3])
        : "r"(a[0]), "r"(a[1]), "r"(a[2]), "r"(a[3]), "r"(b[0]), "r"(b[1]));
}
__device__ __forceinline__ void ldsm_x4(unsigned r[4], unsigned saddr) {
    asm volatile("ldmatrix.sync.aligned.m8n8.x4.shared.b16 {%0,%1,%2,%3}, [%4];"
        : "=r"(r[0]), "=r"(r[1]), "=r"(r[2]), "=r"(r[3]) : "r"(saddr));
}
__device__ __forceinline__ void ldsm_x4t(unsigned r[4], unsigned saddr) {
    asm volatile("ldmatrix.sync.aligned.m8n8.x4.trans.shared.b16 {%0,%1,%2,%3}, [%4];"
        : "=r"(r[0]), "=r"(r[1]), "=r"(r[2]), "=r"(r[3]) : "r"(saddr));
}
__device__ __forceinline__ void cp_async16(unsigned saddr, const void* gaddr) {
    asm volatile("cp.async.cg.shared.global [%0], [%1], 16;" :: "r"(saddr), "l"(gaddr));
}
__device__ __forceinline__ void cp_commit() { asm volatile("cp.async.commit_group;"); }
template <int N>
__device__ __forceinline__ void cp_wait() {
    asm volatile("cp.async.wait_group %0;" :: "n"(N));
}

// ---------------- fp32 -> fp16 bulk convert ----------------------------------
__global__ void f2h_kernel(const float4* __restrict__ src, uint4* __restrict__ dst) {
    const size_t i = (size_t)blockIdx.x * 256 + threadIdx.x;
    float4 a = src[2 * i], b = src[2 * i + 1];
    __half2 h0 = __float22half2_rn(make_float2(a.x, a.y));
    __half2 h1 = __float22half2_rn(make_float2(a.z, a.w));
    __half2 h2 = __float22half2_rn(make_float2(b.x, b.y));
    __half2 h3 = __float22half2_rn(make_float2(b.z, b.w));
    uint4 o;
    o.x = *(unsigned*)&h0; o.y = *(unsigned*)&h1;
    o.z = *(unsigned*)&h2; o.w = *(unsigned*)&h3;
    dst[i] = o;
}
// five 512x512 weights in one launch (grid.y selects)
__global__ void f2h5_kernel(const float* w0, const float* w1, const float* w2,
                            const float* w3, const float* w4) {
    const float* srcs[5] = {w0, w1, w2, w3, w4};
    __half* dsts[5] = {wh_wq, wh_rk, wh_rv, wh_ro, wh_wv};
    const float4* s = (const float4*)srcs[blockIdx.y];
    uint4* d = (uint4*)dsts[blockIdx.y];
    const size_t i = (size_t)blockIdx.x * 256 + threadIdx.x;
    float4 a = s[2 * i], b = s[2 * i + 1];
    __half2 h0 = __float22half2_rn(make_float2(a.x, a.y));
    __half2 h1 = __float22half2_rn(make_float2(a.z, a.w));
    __half2 h2 = __float22half2_rn(make_float2(b.x, b.y));
    __half2 h3 = __float22half2_rn(make_float2(b.z, b.w));
    uint4 o;
    o.x = *(unsigned*)&h0; o.y = *(unsigned*)&h1;
    o.z = *(unsigned*)&h2; o.w = *(unsigned*)&h3;
    d[i] = o;
}
// 512x512 fp32 -> fp16 transpose (wk -> wkT, rq -> rqT); grid.z selects
__global__ void tr_f2h_kernel(const float* __restrict__ wk, const float* __restrict__ rq) {
    __shared__ float t[32][33];
    const float* src = blockIdx.z ? rq : wk;
    __half* dst = blockIdx.z ? wh_rqT : wh_wkT;
    const int bx = blockIdx.x * 32, by = blockIdx.y * 32;
    const int tx = threadIdx.x, ty = threadIdx.y;
    #pragma unroll
    for (int i = 0; i < 32; i += 8)
        t[ty + i][tx] = src[(size_t)(by + ty + i) * 512 + bx + tx];
    __syncthreads();
    #pragma unroll
    for (int i = 0; i < 32; i += 8)
        dst[(size_t)(bx + ty + i) * 512 + by + tx] = __float2half(t[tx][ty + i]);
}
// wh_p2 = [ rkrq | rvro ]
__global__ void pack2_kernel() {
    int idx = blockIdx.x * 256 + threadIdx.x;       // 131072 quads
    int r = idx / 256, c = (idx % 256) * 4;
    const __half* src = (c < 512) ? rkrq_h : rvro_h;
    *(uint2*)&wh_p2[r * 1024 + c] = *(const uint2*)&src[r * 512 + (c & 511)];
}

// ---------------- masked context pooling + hidden->fp16 ----------------------
__global__ void ctx_kernel(const float* __restrict__ hidden, const void* mask_raw) {
    const int b = blockIdx.x;
    const int tid = threadIdx.x;              // 128 threads
    __shared__ float sm[NK];
    __shared__ int smode;
    if (tid == 0) {
        const unsigned char* p = (const unsigned char*)mask_raw;
        int mode = 0;
        for (int i = 0; i < 512; ++i) {
            unsigned char v = p[i];
            if (!v) continue;
            if (v != 1u) { mode = 2; break; }
            if (i & 3)   { mode = 1; break; }
        }
        smode = mode;
    }
    __syncthreads();
    const int mode = smode;
    if (tid < NK) {
        int idx = b * NK + tid;
        float m;
        if (mode == 1)      m = ((const unsigned char*)mask_raw)[idx] ? 1.f : 0.f;
        else if (mode == 0) m = ((const int*)mask_raw)[idx] ? 1.f : 0.f;
        else                m = ((const float*)mask_raw)[idx];
        sm[tid] = m;
        buf_mkf[idx] = m;
    }
    __syncthreads();
    float n = 0.f;
    #pragma unroll
    for (int k = 0; k < NK; ++k) n += sm[k];
    const float inv = 1.f / fmaxf(n, 1.f);
    float4 acc = make_float4(0.f, 0.f, 0.f, 0.f);
    const float4* h4 = (const float4*)(hidden + (size_t)b * NK * ND);
    #pragma unroll
    for (int k = 0; k < NK; ++k) {
        float m = sm[k];
        float4 v = h4[k * 128 + tid];
        acc.x += m * v.x; acc.y += m * v.y; acc.z += m * v.z; acc.w += m * v.w;
        __half2 a0 = __float22half2_rn(make_float2(v.x, v.y));
        __half2 a1 = __float22half2_rn(make_float2(v.z, v.w));
        uint2 ho; ho.x = *(unsigned*)&a0; ho.y = *(unsigned*)&a1;
        *(uint2*)&hid_h[((size_t)b * NK + k) * ND + tid * 4] = ho;
    }
    __half2 h0 = __float22half2_rn(make_float2(acc.x * inv, acc.y * inv));
    __half2 h1 = __float22half2_rn(make_float2(acc.z * inv, acc.w * inv));
    uint2 o; o.x = *(unsigned*)&h0; o.y = *(unsigned*)&h1;
    *(uint2*)&ctx_h[(size_t)b * ND + tid * 4] = o;
}

// ---------------- FP16 tensor-core GEMM, 128x128 tile, BK=32 -----------------
// (R14-proven config: 8 warps, 64x32 warp tile, 4-stage cp.async, 2 CTA/SM)
#define ASTRH 40
#define BSTRH 136
#define NSTG 4
#define ABYTES (128 * ASTRH * 2)
#define BBYTES (32 * BSTRH * 2)
#define STGB   (ABYTES + BBYTES)
#define HSMEM  (NSTG * STGB)

__global__ void __launch_bounds__(256, 2)
hgemm(const __half* __restrict__ A, const __half* __restrict__ B,
      float* __restrict__ C, __half* __restrict__ Ch, int M, int N, int K,
      const float* __restrict__ bias1, const float* __restrict__ bias2,
      int do_gelu) {
    extern __shared__ __align__(16) char smem[];

    const int bm = blockIdx.y * 128;
    const int bn = blockIdx.x * 128;
    const int tid  = threadIdx.x;
    const int warp = tid >> 5;
    const int lane = tid & 31;
    const int gid  = lane >> 2;
    const int tig  = lane & 3;
    const int wm   = (warp >> 2) * 64;
    const int wn   = (warp & 3) * 32;

    const unsigned sBase = (unsigned)__cvta_generic_to_shared(smem);
    const unsigned aOff =
        (unsigned)(((wm + ((lane >> 3) & 1) * 8 + (lane & 7)) * ASTRH + (lane >> 4) * 8) * 2);
    const unsigned bOff =
        (unsigned)(((lane & 15) * BSTRH + wn + ((lane >> 4) * 8)) * 2);

    float acc[4][4][4];
    #pragma unroll
    for (int i = 0; i < 4; ++i)
        #pragma unroll
        for (int j = 0; j < 4; ++j)
            #pragma unroll
            for (int r = 0; r < 4; ++r) acc[i][j][r] = 0.f;

    const int nk = K >> 5;

    auto fill = [&](int st, int k0) {
        const unsigned stb = sBase + (unsigned)(st * STGB);
        #pragma unroll
        for (int it = 0; it < 2; ++it) {
            const int idx = tid + 256 * it;
            const int row = idx >> 2, kq = (idx & 3) * 8;
            cp_async16(stb + (unsigned)((row * ASTRH + kq) * 2),
                       A + (size_t)(bm + row) * K + k0 + kq);
        }
        #pragma unroll
        for (int it = 0; it < 2; ++it) {
            const int idx = tid + 256 * it;
            const int kr = idx >> 4, n8 = (idx & 15) * 8;
            cp_async16(stb + (unsigned)(ABYTES + (kr * BSTRH + n8) * 2),
                       B + (size_t)(k0 + kr) * N + bn + n8);
        }
    };

    #pragma unroll
    for (int s = 0; s < NSTG - 1; ++s) {
        fill(s, s * 32);
        cp_commit();
    }
    cp_wait<NSTG - 2>();
    __syncthreads();

    for (int kt = 0; kt < nk; ++kt) {
        const int st = kt & (NSTG - 1);
        const unsigned stA = sBase + (unsigned)(st * STGB);
        const unsigned stB = stA + ABYTES;

        #pragma unroll
        for (int ks = 0; ks < 2; ++ks) {
            unsigned afr[4][4], bfr[4][2];
            #pragma unroll
            for (int i = 0; i < 4; ++i)
                ldsm_x4(afr[i], stA + aOff + (unsigned)(i * 16 * ASTRH * 2 + ks * 32));
            #pragma unroll
            for (int jj = 0; jj < 2; ++jj) {
                unsigned r[4];
                ldsm_x4t(r, stB + bOff + (unsigned)(ks * 16 * BSTRH * 2 + jj * 32));
                bfr[2 * jj][0] = r[0]; bfr[2 * jj][1] = r[1];
                bfr[2 * jj + 1][0] = r[2]; bfr[2 * jj + 1][1] = r[3];
            }
            #pragma unroll
            for (int i = 0; i < 4; ++i)
                #pragma unroll
                for (int j = 0; j < 4; ++j)
                    mma_f16(acc[i][j], afr[i], bfr[j]);
        }

        if (kt + NSTG - 1 < nk)
            fill((kt + NSTG - 1) & (NSTG - 1), (kt + NSTG - 1) << 5);
        cp_commit();
        cp_wait<NSTG - 2>();
        __syncthreads();
    }

    #pragma unroll
    for (int i = 0; i < 4; ++i) {
        #pragma unroll
        for (int j = 0; j < 4; ++j) {
            #pragma unroll
            for (int half = 0; half < 2; ++half) {
                const int row = bm + wm + i * 16 + gid + half * 8;
                const int col = bn + wn + j * 8 + tig * 2;
                float v0 = acc[i][j][half * 2 + 0];
                float v1 = acc[i][j][half * 2 + 1];
                if (bias1) { v0 += bias1[col]; v1 += bias1[col + 1]; }
                if (bias2) { v0 += bias2[col]; v1 += bias2[col + 1]; }
                if (do_gelu) {
                    v0 = 0.5f * v0 * (1.f + erff(v0 * 0.70710678118654752f));
                    v1 = 0.5f * v1 * (1.f + erff(v1 * 0.70710678118654752f));
                }
                if (C)
                    *(float2*)(C + (size_t)row * N + col) = make_float2(v0, v1);
                if (Ch) {
                    __half2 hv = __float22half2_rn(make_float2(v0, v1));
                    *(__half2*)(Ch + (size_t)row * N + col) = hv;
                }
            }
        }
    }
}

// ---------------- attn1a: logits, masked softmax, pooled = attn_w @ hidden ---
__global__ void __launch_bounds__(256) attn1a_kernel() {
    __shared__ __align__(16) float sq[NS * ND];
    __shared__ __align__(16) float sh[NK * ND];
    __shared__ float slog[64], swt[64];
    const int b = blockIdx.x;
    const int tid = threadIdx.x;
    const int warp = tid >> 5;
    const int lane = tid & 31;

    {
        #pragma unroll
        for (int i = 0; i < 2; ++i) {
            const int idx = tid + 256 * i;
            const int s = idx >> 7, c4 = idx & 127;
            uint2 q = *(const uint2*)&qw_h[((size_t)b * NS + s) * ND + 4 * c4];
            ((float4*)sq)[idx] = h4f(q);
        }
        #pragma unroll
        for (int i = 0; i < 8; ++i) {
            const int idx = tid + 256 * i;
            const int k = idx >> 7, c4 = idx & 127;
            uint2 v = *(const uint2*)&hid_h[((size_t)(b * NK + k)) * ND + 4 * c4];
            ((float4*)sh)[idx] = h4f(v);
        }
    }
    __syncthreads();

    {
        const int p0 = warp * 8;
        float acc[8];
        #pragma unroll
        for (int u = 0; u < 8; ++u) acc[u] = 0.f;
        #pragma unroll
        for (int j = 0; j < 4; ++j) {
            const int c = lane + 32 * j;
            #pragma unroll
            for (int u = 0; u < 8; ++u) {
                const int p = p0 + u, s = p >> 4, k = p & 15;
                float4 q4 = ((const float4*)sq)[s * 128 + c];
                float4 k4 = ((const float4*)sh)[k * 128 + c];
                acc[u] += q4.x * k4.x + q4.y * k4.y + q4.z * k4.z + q4.w * k4.w;
            }
        }
        #pragma unroll
        for (int u = 0; u < 8; ++u) acc[u] = warp_sum(acc[u]);
        if (lane == 0) {
            #pragma unroll
            for (int u = 0; u < 8; ++u) slog[p0 + u] = acc[u];
        }
    }
    __syncthreads();

    if (tid < NS) {
        const int s = tid;
        const float scale = 0.04419417382415922f;
        float lg[NK];
        float mx = -1e30f;
        int any = 0;
        #pragma unroll
        for (int k = 0; k < NK; ++k) {
            float m = buf_mkf[b * NK + k];
            float l = (m > 0.5f) ? slog[s * NK + k] * scale : -1e30f;
            if (m > 0.5f) any = 1;
            lg[k] = l;
            mx = fmaxf(mx, l);
        }
        float den = 0.f;
        #pragma unroll
        for (int k = 0; k < NK; ++k) { lg[k] = expf(lg[k] - mx); den += lg[k]; }
        const float inv = any ? (1.f / den) : 0.f;
        #pragma unroll
        for (int k = 0; k < NK; ++k) swt[s * NK + k] = lg[k] * inv;
    }
    __syncthreads();

    {
        #pragma unroll
        for (int i = 0; i < 2; ++i) {
            const int idx = tid + 256 * i;
            const int s = idx >> 7, c4 = idx & 127;
            float4 o = make_float4(0.f, 0.f, 0.f, 0.f);
            #pragma unroll
            for (int k = 0; k < NK; ++k) {
                const float w = swt[s * NK + k];
                float4 v4 = ((const float4*)sh)[k * 128 + c4];
                o.x += w * v4.x; o.y += w * v4.y; o.z += w * v4.z; o.w += w * v4.w;
            }
            __half2 h0 = __float22half2_rn(make_float2(o.x, o.y));
            __half2 h1 = __float22half2_rn(make_float2(o.z, o.w));
            uint2 oh; oh.x = *(unsigned*)&h0; oh.y = *(unsigned*)&h1;
            *(uint2*)&pool_h[((size_t)b * NS + s) * ND + 4 * c4] = oh;
        }
    }
}

// ---------------- attn1b: wsu = LN(ws + pooledv) ------------------------------
__global__ void __launch_bounds__(128) attn1b_kernel(const float* __restrict__ gamma,
                                                     const float* __restrict__ beta) {
    const int b = blockIdx.x;
    const int warp = threadIdx.x >> 5;
    const int lane = threadIdx.x & 31;
    const int s = warp;

    const float4* wsb = (const float4*)(buf_ws + (size_t)b * 2048 + s * ND);
    const __half* pv = poov_h + ((size_t)b * NS + s) * ND;
    float4 y[4];
    #pragma unroll
    for (int j = 0; j < 4; ++j) {
        const int c4 = lane + 32 * j;
        float4 a = wsb[c4];
        float4 p = h4f(*(const uint2*)(pv + 4 * c4));
        y[j] = make_float4(a.x + p.x, a.y + p.y, a.z + p.z, a.w + p.w);
    }
    float sum = 0.f;
    #pragma unroll
    for (int j = 0; j < 4; ++j) sum += y[j].x + y[j].y + y[j].z + y[j].w;
    const float mu = warp_sum(sum) * (1.f / ND);
    float sqs = 0.f;
    #pragma unroll
    for (int j = 0; j < 4; ++j) {
        float cx = y[j].x - mu, cy = y[j].y - mu, cz = y[j].z - mu, cw = y[j].w - mu;
        sqs += cx * cx + cy * cy + cz * cz + cw * cw;
    }
    const float var = warp_sum(sqs) * (1.f / ND);
    const float rstd = rsqrtf(var + 1e-5f);
    #pragma unroll
    for (int j = 0; j < 4; ++j) {
        const int d4 = lane + 32 * j;
        float4 g4 = ((const float4*)gamma)[d4];
        float4 b4 = ((const float4*)beta)[d4];
        float4 o;
        o.x = (y[j].x - mu) * rstd * g4.x + b4.x;
        o.y = (y[j].y - mu) * rstd * g4.y + b4.y;
        o.z = (y[j].z - mu) * rstd * g4.z + b4.z;
        o.w = (y[j].w - mu) * rstd * g4.w + b4.w;
        __half2 h0 = __float22half2_rn(make_float2(o.x, o.y));
        __half2 h1 = __float22half2_rn(make_float2(o.z, o.w));
        uint2 oh; oh.x = *(unsigned*)&h0; oh.y = *(unsigned*)&h1;
        *(uint2*)&wsu_h[((size_t)b * NS + s) * ND + d4 * 4] = oh;
    }
}

// ---------------- attention #2: single fp32 hidden read, +residual, LN -------
__global__ void __launch_bounds__(512) attn2_kernel(const float* __restrict__ hidden,
                                                    const float* __restrict__ gamma,
                                                    const float* __restrict__ beta,
                                                    float* __restrict__ out) {
    __shared__ __align__(16) float skr[NS * ND];
    __shared__ __align__(16) float svr[NS * ND];
    const int b = blockIdx.x;
    const int tid = threadIdx.x;
    const int warp = tid >> 5;          // token k
    const int lane = tid & 31;

    {
        const int s = tid >> 7, c4 = tid & 127;
        const __half* base = krv_h + (size_t)(b * NS + s) * 1024;
        ((float4*)skr)[tid] = h4f(*(const uint2*)(base + 4 * c4));
        ((float4*)svr)[tid] = h4f(*(const uint2*)(base + 512 + 4 * c4));
    }
    __syncthreads();

    const int k = warp;
    // one fp32 load of the hidden row; reused for logits AND residual
    const float4* h4p = (const float4*)(hidden + (size_t)(b * NK + k) * ND);
    float4 hreg[4];
    #pragma unroll
    for (int j = 0; j < 4; ++j) hreg[j] = h4p[lane + 32 * j];

    float acc[4] = {0.f, 0.f, 0.f, 0.f};
    #pragma unroll
    for (int j = 0; j < 4; ++j) {
        const int c = lane + 32 * j;
        const float4 q = hreg[j];
        #pragma unroll
        for (int s = 0; s < 4; ++s) {
            float4 kk = ((const float4*)skr)[s * 128 + c];
            acc[s] += q.x * kk.x + q.y * kk.y + q.z * kk.z + q.w * kk.w;
        }
    }
    #pragma unroll
    for (int s = 0; s < 4; ++s) acc[s] = warp_sum(acc[s]);

    const float scale = 0.04419417382415922f;
    float w[4];
    float mx = -1e30f;
    #pragma unroll
    for (int s = 0; s < 4; ++s) { w[s] = acc[s] * scale; mx = fmaxf(mx, w[s]); }
    float den = 0.f;
    #pragma unroll
    for (int s = 0; s < 4; ++s) { w[s] = expf(w[s] - mx); den += w[s]; }
    const float inv = 1.f / den;
    #pragma unroll
    for (int s = 0; s < 4; ++s) w[s] *= inv;

    float4 y[4];
    #pragma unroll
    for (int j = 0; j < 4; ++j) {
        const int c4 = lane + 32 * j;
        float4 v0 = ((const float4*)svr)[c4];
        float4 v1 = ((const float4*)svr)[128 + c4];
        float4 v2 = ((const float4*)svr)[256 + c4];
        float4 v3 = ((const float4*)svr)[384 + c4];
        const float4 h = hreg[j];
        y[j].x = h.x + w[0] * v0.x + w[1] * v1.x + w[2] * v2.x + w[3] * v3.x;
        y[j].y = h.y + w[0] * v0.y + w[1] * v1.y + w[2] * v2.y + w[3] * v3.y;
        y[j].z = h.z + w[0] * v0.z + w[1] * v1.z + w[2] * v2.z + w[3] * v3.z;
        y[j].w = h.w + w[0] * v0.w + w[1] * v1.w + w[2] * v2.w + w[3] * v3.w;
    }
    float sum = 0.f;
    #pragma unroll
    for (int j = 0; j < 4; ++j) sum += y[j].x + y[j].y + y[j].z + y[j].w;
    const float mu = warp_sum(sum) * (1.f / ND);
    float sqs = 0.f;
    #pragma unroll
    for (int j = 0; j < 4; ++j) {
        float cx = y[j].x - mu, cy = y[j].y - mu, cz = y[j].z - mu, cw = y[j].w - mu;
        sqs += cx * cx + cy * cy + cz * cz + cw * cw;
    }
    const float var = warp_sum(sqs) * (1.f / ND);
    const float rstd = rsqrtf(var + 1e-5f);
    float4* outp = (float4*)(out + (size_t)(b * NK + k) * ND);
    #pragma unroll
    for (int j = 0; j < 4; ++j) {
        const int d4 = lane + 32 * j;
        float4 g4 = ((const float4*)gamma)[d4];
        float4 bb = ((const float4*)beta)[d4];
        float4 o;
        o.x = (y[j].x - mu) * rstd * g4.x + bb.x;
        o.y = (y[j].y - mu) * rstd * g4.y + bb.y;
        o.z = (y[j].z - mu) * rstd * g4.z + bb.z;
        o.w = (y[j].w - mu) * rstd * g4.w + bb.w;
        outp[d4] = o;
    }
}

// ---------------- host launcher ----------------------------------------------
extern "C" void kernel_launch(void* const* d_in, const int* in_sizes, int n_in,
                              void* d_out, int out_size) {
    const float* hidden   = (const float*)d_in[0];
    const void*  mask     = d_in[1];
    const float* fallback = (const float*)d_in[2];
    const float* gw1      = (const float*)d_in[3];
    const float* gb1      = (const float*)d_in[4];
    const float* gw2      = (const float*)d_in[5];
    const float* gb2      = (const float*)d_in[6];
    const float* wq       = (const float*)d_in[7];
    const float* wk       = (const float*)d_in[8];
    const float* wv       = (const float*)d_in[9];
    const float* rq       = (const float*)d_in[10];
    const float* rk       = (const float*)d_in[11];
    const float* rv       = (const float*)d_in[12];
    const float* ro       = (const float*)d_in[13];
    const float* g_ws_w   = (const float*)d_in[14];
    const float* b_ws_w   = (const float*)d_in[15];
    const float* g_out_w  = (const float*)d_in[16];
    const float* b_out_w  = (const float*)d_in[17];
    float* out = (float*)d_out;

    float *ws;
    __half *hidh, *ctxh, *h1h, *wsh, *wsuh, *qwh, *poolh, *poovh, *krvh;
    __half *wgw1, *wgw2, *wwvh, *wwqh, *wrkh, *wrvh, *wroh;
    __half *wkTh, *rqTh, *wqwkh, *rkrqh, *rvroh, *wp2h;
    cudaGetSymbolAddress((void**)&ws,   buf_ws);
    cudaGetSymbolAddress((void**)&hidh, hid_h);
    cudaGetSymbolAddress((void**)&ctxh, ctx_h);
    cudaGetSymbolAddress((void**)&h1h,  h1_h);
    cudaGetSymbolAddress((void**)&wsh,  ws_h);
    cudaGetSymbolAddress((void**)&wsuh, wsu_h);
    cudaGetSymbolAddress((void**)&qwh,  qw_h);
    cudaGetSymbolAddress((void**)&poolh, pool_h);
    cudaGetSymbolAddress((void**)&poovh, poov_h);
    cudaGetSymbolAddress((void**)&krvh, krv_h);
    cudaGetSymbolAddress((void**)&wgw1, wh_gw1);
    cudaGetSymbolAddress((void**)&wgw2, wh_gw2);
    cudaGetSymbolAddress((void**)&wwvh, wh_wv);
    cudaGetSymbolAddress((void**)&wwqh, wh_wq);
    cudaGetSymbolAddress((void**)&wrkh, wh_rk);
    cudaGetSymbolAddress((void**)&wrvh, wh_rv);
    cudaGetSymbolAddress((void**)&wroh, wh_ro);
    cudaGetSymbolAddress((void**)&wkTh, wh_wkT);
    cudaGetSymbolAddress((void**)&rqTh, wh_rqT);
    cudaGetSymbolAddress((void**)&wqwkh, wqwk_h);
    cudaGetSymbolAddress((void**)&rkrqh, rkrq_h);
    cudaGetSymbolAddress((void**)&rvroh, rvro_h);
    cudaGetSymbolAddress((void**)&wp2h, wh_p2);

    cudaFuncSetAttribute(hgemm, cudaFuncAttributeMaxDynamicSharedMemorySize, HSMEM);

    // weight conversions + composed weights
    f2h_kernel<<<256,  256>>>((const float4*)gw1, (uint4*)wgw1);
    f2h_kernel<<<1024, 256>>>((const float4*)gw2, (uint4*)wgw2);
    f2h5_kernel<<<dim3(128, 5), 256>>>(wq, rk, rv, ro, wv);
    tr_f2h_kernel<<<dim3(16, 16, 2), dim3(32, 8)>>>(wk, rq);
    hgemm<<<dim3(4, 4), 256, HSMEM>>>(wwqh, wkTh, nullptr, wqwkh, 512, 512, 512,
                                      nullptr, nullptr, 0);
    hgemm<<<dim3(4, 4), 256, HSMEM>>>(wrkh, rqTh, nullptr, rkrqh, 512, 512, 512,
                                      nullptr, nullptr, 0);
    hgemm<<<dim3(4, 4), 256, HSMEM>>>(wrvh, wroh, nullptr, rvroh, 512, 512, 512,
                                      nullptr, nullptr, 0);
    pack2_kernel<<<512, 256>>>();

    // context pooling (also emits hid_h)
    ctx_kernel<<<NB, 128>>>(hidden, mask);

    // h1 = gelu(ctx @ gw1 + gb1)             (8192 x 1024) -> fp16
    hgemm<<<dim3(8, 64), 256, HSMEM>>>(ctxh, wgw1, nullptr, h1h, 8192, 1024, 512,
                                       gb1, nullptr, 1);
    // ws = h1 @ gw2 + gb2 + fallback         (8192 x 2048) -> fp32 + fp16
    hgemm<<<dim3(16, 64), 256, HSMEM>>>(h1h, wgw2, ws, wsh, 8192, 2048, 1024,
                                        gb2, fallback, 0);
    // Qw' = ws @ (wq@wk^T)                   (32768 x 512) -> fp16
    hgemm<<<dim3(4, 256), 256, HSMEM>>>(wsh, wqwkh, nullptr, qwh, 32768, 512, 512,
                                        nullptr, nullptr, 0);
    // attn1a: softmax + pooled = attn_w @ hidden
    attn1a_kernel<<<NB, 256>>>();
    // pooledv = pooled @ wv                  (32768 x 512) -> fp16
    hgemm<<<dim3(4, 256), 256, HSMEM>>>(poolh, wwvh, nullptr, poovh, 32768, 512, 512,
                                        nullptr, nullptr, 0);
    // attn1b: wsu = LN(ws + pooledv)
    attn1b_kernel<<<NB, 128>>>(g_ws_w, b_ws_w);
    // [Kt|Vro] = ws_upd @ [rk@rq^T | rv@ro]  (32768 x 1024) -> fp16
    hgemm<<<dim3(8, 256), 256, HSMEM>>>(wsuh, wp2h, nullptr, krvh, 32768, 1024, 512,
                                        nullptr, nullptr, 0);
    // attention #2 + residual + layernorm -> out
    attn2_kernel<<<NB, 512>>>(hidden, g_out_w, b_out_w, out);
}